// round 1
// baseline (speedup 1.0000x reference)
#include <cuda_runtime.h>
#include <cuda_bf16.h>
#include <math.h>

#define T_   3072
#define DIM_ 1024
#define H_   8
#define D_   128

// ---------------- scratch (device globals: no allocation allowed) ----------
__device__ float g_qkv[(size_t)T_ * 3 * DIM_];   // 37.7 MB
__device__ float g_q   [(size_t)T_ * DIM_];
__device__ float g_krot[(size_t)T_ * DIM_];
__device__ float g_k   [(size_t)T_ * DIM_];
__device__ float g_v   [(size_t)T_ * DIM_];
__device__ float g_y   [(size_t)T_ * DIM_];
__device__ float g_gate[T_ * H_];

// ---------------- SGEMM: C[m,n] = lam[lidx] * sum_k A[m,k] * B[n,k] --------
// A: [M,K] row-major, B: [N,K] row-major. M,N multiples of 128, K of 16.
__global__ __launch_bounds__(256) void sgemm_abt(
    const float* __restrict__ A, const float* __restrict__ B,
    float* __restrict__ C, int M, int N, int K,
    const float* __restrict__ lam, int lidx)
{
    __shared__ float As[16][128];
    __shared__ float Bs[16][128];
    const int tid = threadIdx.x;
    const int m0 = blockIdx.y * 128;
    const int n0 = blockIdx.x * 128;
    const int ty = tid >> 4, tx = tid & 15;

    float acc[8][8];
#pragma unroll
    for (int i = 0; i < 8; i++)
#pragma unroll
        for (int j = 0; j < 8; j++) acc[i][j] = 0.f;

    for (int k0 = 0; k0 < K; k0 += 16) {
#pragma unroll
        for (int i = 0; i < 2; i++) {
            int f4  = tid + i * 256;     // 0..511
            int row = f4 >> 2;           // 0..127
            int kc  = (f4 & 3) << 2;     // 0,4,8,12
            float4 a = *(const float4*)(A + (size_t)(m0 + row) * K + k0 + kc);
            As[kc + 0][row] = a.x; As[kc + 1][row] = a.y;
            As[kc + 2][row] = a.z; As[kc + 3][row] = a.w;
            float4 b = *(const float4*)(B + (size_t)(n0 + row) * K + k0 + kc);
            Bs[kc + 0][row] = b.x; Bs[kc + 1][row] = b.y;
            Bs[kc + 2][row] = b.z; Bs[kc + 3][row] = b.w;
        }
        __syncthreads();
#pragma unroll
        for (int kk = 0; kk < 16; kk++) {
            float ar[8], br[8];
            *(float4*)(ar + 0) = *(const float4*)&As[kk][ty * 8 + 0];
            *(float4*)(ar + 4) = *(const float4*)&As[kk][ty * 8 + 4];
            *(float4*)(br + 0) = *(const float4*)&Bs[kk][tx * 8 + 0];
            *(float4*)(br + 4) = *(const float4*)&Bs[kk][tx * 8 + 4];
#pragma unroll
            for (int i = 0; i < 8; i++)
#pragma unroll
                for (int j = 0; j < 8; j++)
                    acc[i][j] = fmaf(ar[i], br[j], acc[i][j]);
        }
        __syncthreads();
    }

    const float alpha = lam[lidx];
#pragma unroll
    for (int i = 0; i < 8; i++) {
        float4 c0, c1;
        c0.x = alpha * acc[i][0]; c0.y = alpha * acc[i][1];
        c0.z = alpha * acc[i][2]; c0.w = alpha * acc[i][3];
        c1.x = alpha * acc[i][4]; c1.y = alpha * acc[i][5];
        c1.z = alpha * acc[i][6]; c1.w = alpha * acc[i][7];
        float* cp = C + (size_t)(m0 + ty * 8 + i) * N + n0 + tx * 8;
        *(float4*)(cp + 0) = c0;
        *(float4*)(cp + 4) = c1;
    }
}

// ------------- postprocess: rmsnorm + rotary + gates + ve add --------------
// one block per t, warp w handles head w. lane owns d in {l, l+32, l+64, l+96}
__global__ __launch_bounds__(256) void postproc_kernel(
    const float* __restrict__ x, const float* __restrict__ ve,
    const float* __restrict__ ve_gate_w, const float* __restrict__ attn_gate_w,
    const float* __restrict__ cosb, const float* __restrict__ sinb)
{
    const int t    = blockIdx.x;
    const int w    = threadIdx.x >> 5;   // head
    const int lane = threadIdx.x & 31;
    const float* base = g_qkv + (size_t)t * (3 * DIM_);

    const float c0 = cosb[t * 64 + lane],      s0 = sinb[t * 64 + lane];
    const float c1 = cosb[t * 64 + lane + 32], s1 = sinb[t * 64 + lane + 32];

    // ---- q ----
    {
        const float* qb = base + w * D_;
        float a0 = qb[lane], a1 = qb[lane + 32], a2 = qb[lane + 64], a3 = qb[lane + 96];
        float ss = a0*a0 + a1*a1 + a2*a2 + a3*a3;
#pragma unroll
        for (int off = 16; off; off >>= 1) ss += __shfl_xor_sync(0xffffffffu, ss, off);
        float r = rsqrtf(ss * (1.0f / 128.0f) + 1e-6f);
        a0 *= r; a1 *= r; a2 *= r; a3 *= r;
        float* qp = g_q + (size_t)t * DIM_ + w * D_;
        qp[lane]      =  a0 * c0 + a2 * s0;
        qp[lane + 32] =  a1 * c1 + a3 * s1;
        qp[lane + 64] = -a0 * s0 + a2 * c0;
        qp[lane + 96] = -a1 * s1 + a3 * c1;
    }
    // ---- k (pre-shift rotary) ----
    {
        const float* kb = base + DIM_ + w * D_;
        float a0 = kb[lane], a1 = kb[lane + 32], a2 = kb[lane + 64], a3 = kb[lane + 96];
        float ss = a0*a0 + a1*a1 + a2*a2 + a3*a3;
#pragma unroll
        for (int off = 16; off; off >>= 1) ss += __shfl_xor_sync(0xffffffffu, ss, off);
        float r = rsqrtf(ss * (1.0f / 128.0f) + 1e-6f);
        a0 *= r; a1 *= r; a2 *= r; a3 *= r;
        float* kp = g_krot + (size_t)t * DIM_ + w * D_;
        kp[lane]      =  a0 * c0 + a2 * s0;
        kp[lane + 32] =  a1 * c1 + a3 * s1;
        kp[lane + 64] = -a0 * s0 + a2 * c0;
        kp[lane + 96] = -a1 * s1 + a3 * c1;
    }
    // ---- gates (16-dim dots) ----
    float xv = (lane < 16) ? x[(size_t)t * DIM_ + lane] : 0.f;
    float dv = (lane < 16) ? xv * ve_gate_w[w * 16 + lane]   : 0.f;
    float da = (lane < 16) ? xv * attn_gate_w[w * 16 + lane] : 0.f;
#pragma unroll
    for (int off = 16; off; off >>= 1) {
        dv += __shfl_xor_sync(0xffffffffu, dv, off);
        da += __shfl_xor_sync(0xffffffffu, da, off);
    }
    const float veg = 2.0f / (1.0f + __expf(-dv));
    if (lane == 0) g_gate[t * H_ + w] = 1.0f / (1.0f + __expf(-da));

    // ---- v = v + veg * ve ----
    {
        const float* vb = base + 2 * DIM_ + w * D_;
        const float* vе = ve + (size_t)t * DIM_ + w * D_;
        float* vp = g_v + (size_t)t * DIM_ + w * D_;
        vp[lane]      = vb[lane]      + veg * vе[lane];
        vp[lane + 32] = vb[lane + 32] + veg * vе[lane + 32];
        vp[lane + 64] = vb[lane + 64] + veg * vе[lane + 64];
        vp[lane + 96] = vb[lane + 96] + veg * vе[lane + 96];
    }
}

// ------------- k-shift: quarters 1,3 come from t-1 -------------------------
__global__ __launch_bounds__(256) void kshift_kernel()
{
    int idx = blockIdx.x * blockDim.x + threadIdx.x;   // < T_*DIM_
    int t = idx >> 10;
    int c = idx & 1023;
    int d = c & 127;
    int qtr = d >> 5;
    int st = (qtr == 1 || qtr == 3) ? (t > 0 ? t - 1 : 0) : t;
    g_k[idx] = g_krot[(size_t)st * DIM_ + c];
}

// ------------- flash attention (fp32, 64x64 tiles) --------------------------
#define QSTR 132
#define PSTR 68
#define ATTN_SMEM ((3 * 64 * QSTR + 64 * PSTR) * 4 + 128 * 4)

__device__ __forceinline__ float rmax16(float v) {
#pragma unroll
    for (int off = 8; off; off >>= 1)
        v = fmaxf(v, __shfl_xor_sync(0xffffffffu, v, off, 16));
    return v;
}
__device__ __forceinline__ float rsum16(float v) {
#pragma unroll
    for (int off = 8; off; off >>= 1)
        v += __shfl_xor_sync(0xffffffffu, v, off, 16);
    return v;
}

__global__ __launch_bounds__(256) void attn_kernel(
    const int* __restrict__ seg, const int* __restrict__ bm_ptr)
{
    extern __shared__ float sm[];
    float* Qs = sm;                       // 64 x QSTR
    float* Ks = Qs + 64 * QSTR;
    float* Vs = Ks + 64 * QSTR;
    float* Ps = Vs + 64 * QSTR;           // 64 x PSTR
    int*  qseg = (int*)(Ps + 64 * PSTR);  // 64
    int*  kseg = qseg + 64;               // 64

    const int h   = blockIdx.y;
    const int m0  = blockIdx.x * 64;
    const int tid = threadIdx.x;
    const int ty  = tid >> 4, tx = tid & 15;
    const int bm  = bm_ptr[0];

    // load Q tile [64 x 128]
#pragma unroll
    for (int i = 0; i < 8; i++) {
        int idx = tid + i * 256;          // float4 index, 0..2047
        int r = idx >> 5, c4 = idx & 31;
        *(float4*)&Qs[r * QSTR + c4 * 4] =
            *(const float4*)&g_q[(size_t)(m0 + r) * DIM_ + h * D_ + c4 * 4];
    }
    if (tid < 64) qseg[tid] = seg[m0 + tid];
    __syncthreads();

    float m_i[4], l_i[4], Oacc[4][8];
#pragma unroll
    for (int i = 0; i < 4; i++) {
        m_i[i] = -1e30f; l_i[i] = 0.f;
#pragma unroll
        for (int j = 0; j < 8; j++) Oacc[i][j] = 0.f;
    }

    const int qs0 = seg[m0], qs1 = seg[m0 + 63];
    int kb_lo = m0 - bm; if (kb_lo < 0) kb_lo = 0; kb_lo >>= 6;
    const int kb_hi = m0 >> 6;

    for (int kb = kb_lo; kb <= kb_hi; kb++) {
        const int s0 = kb * 64;
        const int ks0 = seg[s0], ks1 = seg[s0 + 63];
        if (ks1 < qs0 || ks0 > qs1) continue;   // monotonic segment skip (uniform)

        // load K, V tiles
#pragma unroll
        for (int i = 0; i < 8; i++) {
            int idx = tid + i * 256;
            int r = idx >> 5, c4 = idx & 31;
            *(float4*)&Ks[r * QSTR + c4 * 4] =
                *(const float4*)&g_k[(size_t)(s0 + r) * DIM_ + h * D_ + c4 * 4];
            *(float4*)&Vs[r * QSTR + c4 * 4] =
                *(const float4*)&g_v[(size_t)(s0 + r) * DIM_ + h * D_ + c4 * 4];
        }
        if (tid < 64) kseg[tid] = seg[s0 + tid];
        __syncthreads();

        // S = Q K^T  (each thread: 4x4)
        float s_reg[4][4];
#pragma unroll
        for (int i = 0; i < 4; i++)
#pragma unroll
            for (int j = 0; j < 4; j++) s_reg[i][j] = 0.f;

        for (int d4 = 0; d4 < 32; d4++) {
            float4 qa[4], ka[4];
#pragma unroll
            for (int i = 0; i < 4; i++)
                qa[i] = *(const float4*)&Qs[(ty * 4 + i) * QSTR + d4 * 4];
#pragma unroll
            for (int j = 0; j < 4; j++)
                ka[j] = *(const float4*)&Ks[(tx * 4 + j) * QSTR + d4 * 4];
#pragma unroll
            for (int i = 0; i < 4; i++)
#pragma unroll
                for (int j = 0; j < 4; j++) {
                    s_reg[i][j] = fmaf(qa[i].x, ka[j].x, s_reg[i][j]);
                    s_reg[i][j] = fmaf(qa[i].y, ka[j].y, s_reg[i][j]);
                    s_reg[i][j] = fmaf(qa[i].z, ka[j].z, s_reg[i][j]);
                    s_reg[i][j] = fmaf(qa[i].w, ka[j].w, s_reg[i][j]);
                }
        }

        // mask + scale + online softmax
#pragma unroll
        for (int i = 0; i < 4; i++) {
            const int tq = m0 + ty * 4 + i;
            const int sq = qseg[ty * 4 + i];
            float rowmax = -1e30f;
#pragma unroll
            for (int j = 0; j < 4; j++) {
                const int tk = s0 + tx * 4 + j;
                bool valid = (tk <= tq) && (tk >= tq - bm) && (kseg[tx * 4 + j] == sq);
                float sv = valid ? s_reg[i][j] * 0.1f : -1e30f;
                s_reg[i][j] = sv;
                rowmax = fmaxf(rowmax, sv);
            }
            rowmax = rmax16(rowmax);
            const float newm  = fmaxf(m_i[i], rowmax);
            const float alpha = __expf(m_i[i] - newm);
            m_i[i] = newm;
            float rs = 0.f;
#pragma unroll
            for (int j = 0; j < 4; j++) {
                float p = __expf(s_reg[i][j] - newm);
                Ps[(ty * 4 + i) * PSTR + tx * 4 + j] = p;
                rs += p;
            }
            rs = rsum16(rs);
            l_i[i] = l_i[i] * alpha + rs;
#pragma unroll
            for (int j = 0; j < 8; j++) Oacc[i][j] *= alpha;
        }
        __syncthreads();

        // O += P V   (each thread: rows ty*4+i, cols tx + 16*j)
        for (int s = 0; s < 64; s++) {
            float vv[8];
#pragma unroll
            for (int j = 0; j < 8; j++) vv[j] = Vs[s * QSTR + tx + 16 * j];
#pragma unroll
            for (int i = 0; i < 4; i++) {
                float p = Ps[(ty * 4 + i) * PSTR + s];
#pragma unroll
                for (int j = 0; j < 8; j++)
                    Oacc[i][j] = fmaf(p, vv[j], Oacc[i][j]);
            }
        }
        __syncthreads();
    }

    // epilogue: normalize, gate, store
#pragma unroll
    for (int i = 0; i < 4; i++) {
        const int tq = m0 + ty * 4 + i;
        const float g = g_gate[tq * H_ + h];
        const float inv = g / l_i[i];
#pragma unroll
        for (int j = 0; j < 8; j++)
            g_y[(size_t)tq * DIM_ + h * D_ + tx + 16 * j] = Oacc[i][j] * inv;
    }
}

// ---------------------------------------------------------------------------
extern "C" void kernel_launch(void* const* d_in, const int* in_sizes, int n_in,
                              void* d_out, int out_size)
{
    const float* x    = (const float*)d_in[0];
    const float* qkvo = (const float*)d_in[1];
    const float* lam  = (const float*)d_in[2];
    const float* ve   = (const float*)d_in[3];
    const float* agw  = (const float*)d_in[4];
    const float* vgw  = (const float*)d_in[5];
    const float* cosb = (const float*)d_in[6];
    const float* sinb = (const float*)d_in[7];
    const int*   seg  = (const int*)d_in[8];
    const int*   bmp  = (const int*)d_in[9];
    float*       out  = (float*)d_out;

    float *p_qkv, *p_y;
    cudaGetSymbolAddress((void**)&p_qkv, g_qkv);
    cudaGetSymbolAddress((void**)&p_y,   g_y);

    // 1. qkv = lam0 * x @ Wqkv^T   [3072 x 3072]
    sgemm_abt<<<dim3(3072 / 128, 3072 / 128), 256>>>(
        x, qkvo, p_qkv, T_, 3 * DIM_, DIM_, lam, 0);

    // 2. rmsnorm + rotary + gates + ve add
    postproc_kernel<<<T_, 256>>>(x, ve, vgw, agw, cosb, sinb);

    // 3. k quarter-shift
    kshift_kernel<<<(T_ * DIM_) / 256, 256>>>();

    // 4. attention
    cudaFuncSetAttribute(attn_kernel,
                         cudaFuncAttributeMaxDynamicSharedMemorySize, ATTN_SMEM);
    attn_kernel<<<dim3(T_ / 64, H_), 256, ATTN_SMEM>>>(seg, bmp);

    // 5. out = lam1 * y @ Wo^T   [3072 x 1024]
    sgemm_abt<<<dim3(1024 / 128, 3072 / 128), 256>>>(
        p_y, qkvo + 3 * DIM_ * DIM_, out, T_, DIM_, DIM_, lam, 1);
}